// round 15
// baseline (speedup 1.0000x reference)
#include <cuda_runtime.h>
#include <stdint.h>

// Problem constants
#define TT   384
#define NN   384
#define RR   384
#define D1   128
#define D2   32
#define SZ1  (D1*TT)   // 49152
#define SZ2  (D2*TT)   // 12288
#define NBLK 384
#define NTHR 416       // 13 warps
#define NB   392

// Scratch (static device globals; zero-initialized)
__device__ float g_v1[SZ1];
__device__ float g_v2[SZ2];
__device__ float g_nh1[TT*NN];   // transposed: [t][n]
__device__ float g_nh2[TT*NN];
__device__ float g_loss;
__device__ unsigned g_bar1;
__device__ unsigned g_bar2;
__device__ unsigned g_done;

// ---------------------------------------------------------------------------
// Threefry2x32, key = (0, 42), partitionable: bits(i) = o0^o1, counter (0,i)
// ---------------------------------------------------------------------------
__device__ __forceinline__ uint32_t rotl32(uint32_t x, int d) {
    return (x << d) | (x >> (32 - d));
}

__device__ __forceinline__ void threefry_0_42(uint32_t x0, uint32_t x1,
                                              uint32_t& o0, uint32_t& o1) {
    const uint32_t ks0 = 0u;
    const uint32_t ks1 = 42u;
    const uint32_t ks2 = 0u ^ 42u ^ 0x1BD11BDAu;
    x0 += ks0; x1 += ks1;
#define TF_R4(a,b,c,d)                               \
    x0 += x1; x1 = rotl32(x1,(a)); x1 ^= x0;          \
    x0 += x1; x1 = rotl32(x1,(b)); x1 ^= x0;          \
    x0 += x1; x1 = rotl32(x1,(c)); x1 ^= x0;          \
    x0 += x1; x1 = rotl32(x1,(d)); x1 ^= x0;
    TF_R4(13,15,26,6)   x0 += ks1; x1 += ks2 + 1u;
    TF_R4(17,29,16,24)  x0 += ks2; x1 += ks0 + 2u;
    TF_R4(13,15,26,6)   x0 += ks0; x1 += ks1 + 3u;
    TF_R4(17,29,16,24)  x0 += ks1; x1 += ks2 + 4u;
    TF_R4(13,15,26,6)   x0 += ks2; x1 += ks0 + 5u;
#undef TF_R4
    o0 = x0; o1 = x1;
}

// XLA ErfInv float32 polynomial (log1p -> fast MUFU log)
__device__ __forceinline__ float erfinv_fast(float x) {
    float w = -__logf(fmaf(-x, x, 1.0f));
    float p;
    if (w < 5.0f) {
        w -= 2.5f;
        p = 2.81022636e-08f;
        p = fmaf(p, w, 3.43273939e-07f);
        p = fmaf(p, w, -3.5233877e-06f);
        p = fmaf(p, w, -4.39150654e-06f);
        p = fmaf(p, w, 0.00021858087f);
        p = fmaf(p, w, -0.00125372503f);
        p = fmaf(p, w, -0.00417768164f);
        p = fmaf(p, w, 0.246640727f);
        p = fmaf(p, w, 1.50140941f);
    } else {
        w = sqrtf(w) - 3.0f;
        p = -0.000200214257f;
        p = fmaf(p, w, 0.000100950558f);
        p = fmaf(p, w, 0.00134934322f);
        p = fmaf(p, w, -0.00367342844f);
        p = fmaf(p, w, 0.00573950773f);
        p = fmaf(p, w, -0.0076224613f);
        p = fmaf(p, w, 0.00943887047f);
        p = fmaf(p, w, 1.00167406f);
        p = fmaf(p, w, 2.83297682f);
    }
    return p * x;
}

__device__ __forceinline__ float bits_to_normal(uint32_t b) {
    float f = __uint_as_float((b >> 9) | 0x3F800000u) - 1.0f;   // [0,1)
    const float lo = -0.99999994f;                               // nextafter(-1,0)
    const float span = 1.0f - lo;
    float u = fmaf(f, span, lo);
    u = fmaxf(lo, u);
    return 1.41421356f * erfinv_fast(u);   // sqrt(2)
}

__device__ __forceinline__ float tanh_hw(float x) {
    float y;
    asm("tanh.approx.f32 %0, %1;" : "=f"(y) : "f"(x));
    return y;
}

// ---------------------------------------------------------------------------
// Device-wide barrier. SAFE only because ALL NBLK blocks are concurrently
// resident (launch_bounds(416,3): regs<=52 -> >=3 blocks/SM -> capacity
// 444 >= 384). prev_ctr (if given) is reset by the LAST arriver — at that
// point every block has exited prev_ctr's spin (it arrived here), so the
// reset cannot strand a spinner.
// ---------------------------------------------------------------------------
__device__ __forceinline__ void global_barrier(unsigned* ctr, unsigned* prev_ctr) {
    __syncthreads();
    if (threadIdx.x == 0) {
        __threadfence();
        unsigned old = atomicAdd(ctr, 1u);
        if (old == NBLK - 1u && prev_ctr) *prev_ctr = 0u;
        while (*(volatile unsigned*)ctr < (unsigned)NBLK) __nanosleep(64);
        __threadfence();
    }
    __syncthreads();
}

// ---------------------------------------------------------------------------
// Shared-memory union of the two phase layouts
// ---------------------------------------------------------------------------
struct GemmS {
    float xs[32][33];
    float vs[32][33];
    float nrm[32];
    float inv[32];
};
struct EctS {
    unsigned pcnt[NB];
    unsigned est[NB + 1];
    float    sval1[NN];
    float    sval2[NN];
    unsigned wsum[13];
    unsigned wofs[13];
    float    ps[13];
};

__global__ void __launch_bounds__(NTHR, 3)
fused_kernel(const float* __restrict__ s1, const float* __restrict__ s2,
             float* __restrict__ out) {
    __shared__ __align__(16) char smraw[sizeof(GemmS) > sizeof(EctS)
                                        ? sizeof(GemmS) : sizeof(EctS)];
    int bid = blockIdx.x;
    int tid = threadIdx.x;

    // ================= Phase A: generate directions (160 elems/block) ======
    if (bid == 0 && tid == 0) g_loss = 0.0f;
    if (tid < 160) {
        int i = bid * 160 + tid;
        uint32_t idx = (i < SZ1) ? (uint32_t)i : (uint32_t)(i - SZ1);
        uint32_t o0, o1;
        threefry_0_42(0u, idx, o0, o1);
        float v = bits_to_normal(o0 ^ o1);
        if (i < SZ1) g_v1[i] = v; else g_v2[i - SZ1] = v;
    }
    global_barrier(&g_bar1, 0);

    // ================= Phase B: gemm tiles (288 tiles, bid < 288) ==========
    if (bid < 288) {
        GemmS& sg = *reinterpret_cast<GemmS*>(smraw);
        int space = bid & 1;
        int tl    = bid >> 1;            // 0..143
        const float* X = space ? s2 : s1;
        const float* V = space ? g_v2 : g_v1;
        float* OUT     = space ? g_nh2 : g_nh1;
        const int D    = space ? D2 : D1;
        const int KT   = D / 32;

        int n0 = (tl % 12) * 32;
        int t0 = (tl / 12) * 32;
        bool act = tid < 256;
        int lin = act ? tid : 0;
        int tx = lin & 15;
        int ty = lin >> 4;
        int lcol = lin & 31;
        int lgrp = lin >> 5;

        if (act && lin < 32) sg.nrm[lin] = 0.0f;
        __syncthreads();

        float nsum = 0.0f;
        float a00 = 0.0f, a01 = 0.0f, a10 = 0.0f, a11 = 0.0f;

        for (int u = 0; u < KT; u++) {
            int k0 = u * 32;
            if (act) {
                #pragma unroll
                for (int j = 0; j < 4; j++) {
                    int row = lgrp * 4 + j;
                    sg.xs[row][lcol] = X[(n0 + row) * D + (k0 + lcol)];
                    float v = V[(k0 + row) * TT + (t0 + lcol)];
                    sg.vs[row][lcol] = v;
                    nsum = fmaf(v, v, nsum);
                }
            }
            __syncthreads();
            if (act) {
                #pragma unroll
                for (int k = 0; k < 32; k++) {
                    float x0 = sg.xs[tx][k];
                    float x1 = sg.xs[tx + 16][k];
                    float v0 = sg.vs[k][ty];
                    float v1 = sg.vs[k][ty + 16];
                    a00 = fmaf(x0, v0, a00);
                    a01 = fmaf(x0, v1, a01);
                    a10 = fmaf(x1, v0, a10);
                    a11 = fmaf(x1, v1, a11);
                }
            }
            __syncthreads();
        }
        if (act) atomicAdd(&sg.nrm[lcol], nsum);
        __syncthreads();
        if (act && lin < 32) sg.inv[lin] = rsqrtf(sg.nrm[lin]);
        __syncthreads();

        if (act) {
            float i0 = sg.inv[ty], i1 = sg.inv[ty + 16];
            OUT[(t0 + ty)      * NN + (n0 + tx)]      = a00 * i0;
            OUT[(t0 + ty + 16) * NN + (n0 + tx)]      = a01 * i1;
            OUT[(t0 + ty)      * NN + (n0 + tx + 16)] = a10 * i0;
            OUT[(t0 + ty + 16) * NN + (n0 + tx + 16)] = a11 * i1;
        }
    }
    global_barrier(&g_bar2, &g_bar1);

    // ================= Phase C: ECT diff + loss (CSR + gather) =============
    {
        EctS& se = *reinterpret_cast<EctS*>(smraw);
        int t    = bid;
        int lane = tid & 31, wid = tid >> 5;

        float nh1 = 0.0f, nh2 = 0.0f;
        if (tid < NN) {
            nh1 = g_nh1[t * NN + tid];
            nh2 = g_nh2[t * NN + tid];
        }
        if (tid < NB) se.pcnt[tid] = 0u;
        __syncthreads();

        const float AI   = 383.0f / 2.0f;
        const float H250 = 500.0f / 383.0f;

        int B1 = 0, B2 = 0;
        unsigned rk1 = 0, rk2 = 0;
        float b1 = 0.0f, b2 = 0.0f;
        if (tid < NN) {
            int ia1 = (int)floorf((nh1 + 1.0f) * AI);
            int ia2 = (int)floorf((nh2 + 1.0f) * AI);
            B1 = (ia1 <= -4) ? 0 : ((ia1 >= 387) ? 391 : ia1 + 4);
            B2 = (ia2 <= -4) ? 0 : ((ia2 >= 387) ? 391 : ia2 + 4);
            b1 = -250.0f * (1.0f + nh1);
            b2 = -250.0f * (1.0f + nh2);
            rk1 = atomicAdd(&se.pcnt[B1], 0x10000u) >> 16;
            rk2 = atomicAdd(&se.pcnt[B2], 1u) & 0xFFFFu;
        }
        __syncthreads();

        unsigned v = (tid < NB) ? se.pcnt[tid] : 0u;
        unsigned iv = v;
        #pragma unroll
        for (int o = 1; o < 32; o <<= 1) {
            unsigned y = __shfl_up_sync(0xffffffffu, iv, o);
            if (lane >= o) iv += y;
        }
        if (lane == 31) se.wsum[wid] = iv;
        __syncthreads();
        if (tid < 32) {
            unsigned a = (tid < 13) ? se.wsum[tid] : 0u;
            #pragma unroll
            for (int o = 1; o < 32; o <<= 1) {
                unsigned y = __shfl_up_sync(0xffffffffu, a, o);
                if (tid >= o) a += y;
            }
            if (tid < 13) se.wofs[tid] = a;
        }
        __syncthreads();
        unsigned incl = iv + (wid ? se.wofs[wid - 1] : 0u);
        if (tid < NB) se.est[tid] = incl - v;
        if (tid == NB - 1) se.est[NB] = incl;
        __syncthreads();

        if (tid < NN) {
            se.sval1[(se.est[B1] >> 16) + rk1]     = b1;
            se.sval2[(se.est[B2] & 0xFFFFu) + rk2] = b2;
        }
        __syncthreads();

        float sq = 0.0f;
        if (tid < RR) {
            unsigned eL = se.est[tid + 1];
            unsigned eR = se.est[tid + 8];
            int j0 = (int)(eL >> 16),     j1 = (int)(eR >> 16);
            int k0 = (int)(eL & 0xFFFFu), k1 = (int)(eR & 0xFFFFu);
            int c1 = j1 - j0;
            int c2 = k1 - k0;
            float acc = (float)(j0 - k0) + 0.5f * (float)(c1 - c2);
            float rz  = (float)tid * H250;
            int tot = c1 + c2;
            for (int i = 0; i < tot; i++) {
                bool in1 = i < c1;
                float bv = in1 ? se.sval1[j0 + i] : se.sval2[k0 + i - c1];
                float sg = in1 ? 0.5f : -0.5f;
                acc = fmaf(sg, tanh_hw(rz + bv), acc);
            }
            sq = acc * acc;
        }

        #pragma unroll
        for (int o = 16; o; o >>= 1) sq += __shfl_down_sync(0xffffffffu, sq, o);
        if (lane == 0) se.ps[wid] = sq;
        __syncthreads();
        if (tid == 0) {
            float s = 0.0f;
            #pragma unroll
            for (int i = 0; i < 13; i++) s += se.ps[i];
            atomicAdd(&g_loss, s);
            __threadfence();
            unsigned prev = atomicAdd(&g_done, 1u);
            if (prev == (unsigned)(NBLK - 1)) {
                g_done = 0u;   // self-resets for graph replay
                g_bar2 = 0u;   // (g_bar1 was reset by bar2's last arriver)
                float total = *((volatile float*)&g_loss);
                out[0] = total * (1.0f / (float)(RR * TT));
            }
        }
    }
}

extern "C" void kernel_launch(void* const* d_in, const int* in_sizes, int n_in,
                              void* d_out, int out_size) {
    const float* s1 = (const float*)d_in[0];   // [384, 128]
    const float* s2 = (const float*)d_in[1];   // [384, 32]
    float* out = (float*)d_out;

    fused_kernel<<<NBLK, NTHR>>>(s1, s2, out);
}

// round 16
// speedup vs baseline: 1.2595x; 1.2595x over previous
#include <cuda_runtime.h>
#include <stdint.h>

// Problem constants
#define TT   384
#define NN   384
#define RR   384
#define D1   128
#define D2   32
#define SZ1  (D1*TT)   // 49152
#define SZ2  (D2*TT)   // 12288

// Scratch (static device globals)
__device__ float g_v1[SZ1];
__device__ float g_v2[SZ2];
__device__ float g_nh1[TT*NN];   // transposed: [t][n]
__device__ float g_nh2[TT*NN];
__device__ float g_loss;
__device__ unsigned g_done = 0;

// ---------------------------------------------------------------------------
// Threefry2x32, key = (0, 42), partitionable: bits(i) = o0^o1, counter (0,i)
// ---------------------------------------------------------------------------
__device__ __forceinline__ uint32_t rotl32(uint32_t x, int d) {
    return (x << d) | (x >> (32 - d));
}

__device__ __forceinline__ void threefry_0_42(uint32_t x0, uint32_t x1,
                                              uint32_t& o0, uint32_t& o1) {
    const uint32_t ks0 = 0u;
    const uint32_t ks1 = 42u;
    const uint32_t ks2 = 0u ^ 42u ^ 0x1BD11BDAu;
    x0 += ks0; x1 += ks1;
#define TF_R4(a,b,c,d)                               \
    x0 += x1; x1 = rotl32(x1,(a)); x1 ^= x0;          \
    x0 += x1; x1 = rotl32(x1,(b)); x1 ^= x0;          \
    x0 += x1; x1 = rotl32(x1,(c)); x1 ^= x0;          \
    x0 += x1; x1 = rotl32(x1,(d)); x1 ^= x0;
    TF_R4(13,15,26,6)   x0 += ks1; x1 += ks2 + 1u;
    TF_R4(17,29,16,24)  x0 += ks2; x1 += ks0 + 2u;
    TF_R4(13,15,26,6)   x0 += ks0; x1 += ks1 + 3u;
    TF_R4(17,29,16,24)  x0 += ks1; x1 += ks2 + 4u;
    TF_R4(13,15,26,6)   x0 += ks2; x1 += ks0 + 5u;
#undef TF_R4
    o0 = x0; o1 = x1;
}

// XLA ErfInv float32 polynomial (log1p -> fast MUFU log)
__device__ __forceinline__ float erfinv_fast(float x) {
    float w = -__logf(fmaf(-x, x, 1.0f));
    float p;
    if (w < 5.0f) {
        w -= 2.5f;
        p = 2.81022636e-08f;
        p = fmaf(p, w, 3.43273939e-07f);
        p = fmaf(p, w, -3.5233877e-06f);
        p = fmaf(p, w, -4.39150654e-06f);
        p = fmaf(p, w, 0.00021858087f);
        p = fmaf(p, w, -0.00125372503f);
        p = fmaf(p, w, -0.00417768164f);
        p = fmaf(p, w, 0.246640727f);
        p = fmaf(p, w, 1.50140941f);
    } else {
        w = sqrtf(w) - 3.0f;
        p = -0.000200214257f;
        p = fmaf(p, w, 0.000100950558f);
        p = fmaf(p, w, 0.00134934322f);
        p = fmaf(p, w, -0.00367342844f);
        p = fmaf(p, w, 0.00573950773f);
        p = fmaf(p, w, -0.0076224613f);
        p = fmaf(p, w, 0.00943887047f);
        p = fmaf(p, w, 1.00167406f);
        p = fmaf(p, w, 2.83297682f);
    }
    return p * x;
}

__device__ __forceinline__ float bits_to_normal(uint32_t b) {
    float f = __uint_as_float((b >> 9) | 0x3F800000u) - 1.0f;   // [0,1)
    const float lo = -0.99999994f;                               // nextafter(-1,0)
    const float span = 1.0f - lo;
    float u = fmaf(f, span, lo);
    u = fmaxf(lo, u);
    return 1.41421356f * erfinv_fast(u);   // sqrt(2)
}

__device__ __forceinline__ float tanh_hw(float x) {
    float y;
    asm("tanh.approx.f32 %0, %1;" : "=f"(y) : "f"(x));
    return y;
}

// ---------------------------------------------------------------------------
// 1) Generate direction matrices (R9 config). Triggers dependent launch
//    immediately: gemm's X-loading prelude overlaps with gen's ALU work.
// ---------------------------------------------------------------------------
__global__ void gen_dirs_kernel() {
#if __CUDA_ARCH__ >= 900
    cudaTriggerProgrammaticLaunchCompletion();
#endif
    int i = blockIdx.x * 256 + threadIdx.x;
    if (i == 0) g_loss = 0.0f;
    uint32_t idx = (i < SZ1) ? (uint32_t)i : (uint32_t)(i - SZ1);
    uint32_t o0, o1;
    threefry_0_42(0u, idx, o0, o1);
    float v = bits_to_normal(o0 ^ o1);
    if (i < SZ1)            g_v1[i] = v;
    else if (i < SZ1 + SZ2) g_v2[i - SZ1] = v;
}

// ---------------------------------------------------------------------------
// 2) nh^T[t][n] = (sum_k X[n,k] V[k,t]) * rsqrt(sum_k V[k,t]^2)
//    32x32 tile, 256 threads, 2x2 register blocking.
//    PDL prelude: ALL X k-tiles staged to smem BEFORE the grid-dependency
//    sync (X doesn't depend on gen). Then sync, then V loop.
// ---------------------------------------------------------------------------
__global__ void __launch_bounds__(256)
gemm_kernel(const float* __restrict__ s1, const float* __restrict__ s2) {
    int space = blockIdx.z;
    const float* X = space ? s2 : s1;
    const float* V = space ? g_v2 : g_v1;
    float* OUT     = space ? g_nh2 : g_nh1;
    const int D    = space ? D2 : D1;
    const int KT   = D / 32;

    int n0 = blockIdx.x * 32;
    int t0 = blockIdx.y * 32;
    int tx = threadIdx.x;           // 0..15
    int ty = threadIdx.y;           // 0..15
    int lin = ty * 16 + tx;         // 0..255

    __shared__ float xs[4][32][33]; // ALL k-tiles of X (prelude)
    __shared__ float vs[32][33];
    __shared__ float nrm[32];
    __shared__ float inv[32];

    int lcol = lin & 31;
    int lgrp = lin >> 5;

    // ---- prelude: stage X (independent of gen) ----
    for (int u = 0; u < KT; u++) {
        #pragma unroll
        for (int j = 0; j < 4; j++) {
            int row = lgrp * 4 + j;
            xs[u][row][lcol] = X[(n0 + row) * D + (u * 32 + lcol)];
        }
    }
    if (lin < 32) nrm[lin] = 0.0f;
    __syncthreads();

#if __CUDA_ARCH__ >= 900
    cudaGridDependencySynchronize();   // wait for gen's V writes
#endif

    float nsum = 0.0f;
    float a00 = 0.0f, a01 = 0.0f, a10 = 0.0f, a11 = 0.0f;

    for (int u = 0; u < KT; u++) {
        int k0 = u * 32;
        #pragma unroll
        for (int j = 0; j < 4; j++) {
            int row = lgrp * 4 + j;
            float v = V[(k0 + row) * TT + (t0 + lcol)];
            vs[row][lcol] = v;
            nsum = fmaf(v, v, nsum);
        }
        __syncthreads();
        #pragma unroll
        for (int k = 0; k < 32; k++) {
            float x0 = xs[u][tx][k];
            float x1 = xs[u][tx + 16][k];
            float v0 = vs[k][ty];
            float v1 = vs[k][ty + 16];
            a00 = fmaf(x0, v0, a00);
            a01 = fmaf(x0, v1, a01);
            a10 = fmaf(x1, v0, a10);
            a11 = fmaf(x1, v1, a11);
        }
        __syncthreads();
    }
    atomicAdd(&nrm[lcol], nsum);
    __syncthreads();
    if (lin < 32) inv[lin] = rsqrtf(nrm[lin]);
    __syncthreads();

#if __CUDA_ARCH__ >= 900
    cudaTriggerProgrammaticLaunchCompletion();   // let ect start its prelude
#endif

    float i0 = inv[ty], i1 = inv[ty + 16];
    OUT[(t0 + ty)      * NN + (n0 + tx)]      = a00 * i0;
    OUT[(t0 + ty + 16) * NN + (n0 + tx)]      = a01 * i1;
    OUT[(t0 + ty)      * NN + (n0 + tx + 16)] = a10 * i0;
    OUT[(t0 + ty + 16) * NN + (n0 + tx + 16)] = a11 * i1;
}

// ---------------------------------------------------------------------------
// 3) ECT difference + loss via counting-sort CSR + gather (R12 validated).
//    PDL prelude: zero pcnt before the grid-dependency sync.
// ---------------------------------------------------------------------------
#define ECT_THREADS 416   // 13 warps
#define NB 392

__global__ void __launch_bounds__(ECT_THREADS)
ect_loss_kernel(float* __restrict__ out) {
    int t    = blockIdx.x;
    int tid  = threadIdx.x;               // 0..415
    int lane = tid & 31, wid = tid >> 5;  // 13 warps

    __shared__ unsigned pcnt[NB];
    __shared__ unsigned est[NB + 1];
    __shared__ float    sval1[NN];
    __shared__ float    sval2[NN];
    __shared__ unsigned wsum[13];
    __shared__ unsigned wofs[13];
    __shared__ float    ps[13];

    // ---- prelude (independent of gemm) ----
    if (tid < NB) pcnt[tid] = 0u;
    __syncthreads();

#if __CUDA_ARCH__ >= 900
    cudaGridDependencySynchronize();   // wait for gemm's nh writes
#endif

    float nh1 = 0.0f, nh2 = 0.0f;
    if (tid < NN) {
        nh1 = __ldg(&g_nh1[t * NN + tid]);
        nh2 = __ldg(&g_nh2[t * NN + tid]);
    }

    const float AI   = 383.0f / 2.0f;
    const float H250 = 500.0f / 383.0f;

    // Phase 1: count (packed atomic; return value = rank within bucket)
    int B1 = 0, B2 = 0;
    unsigned rk1 = 0, rk2 = 0;
    float b1 = 0.0f, b2 = 0.0f;
    if (tid < NN) {
        int ia1 = (int)floorf((nh1 + 1.0f) * AI);
        int ia2 = (int)floorf((nh2 + 1.0f) * AI);
        B1 = (ia1 <= -4) ? 0 : ((ia1 >= 387) ? 391 : ia1 + 4);
        B2 = (ia2 <= -4) ? 0 : ((ia2 >= 387) ? 391 : ia2 + 4);
        b1 = -250.0f * (1.0f + nh1);
        b2 = -250.0f * (1.0f + nh2);
        rk1 = atomicAdd(&pcnt[B1], 0x10000u) >> 16;
        rk2 = atomicAdd(&pcnt[B2], 1u) & 0xFFFFu;
    }
    __syncthreads();

    // Phase 2: exclusive scan of packed counts (no cross-field carry)
    unsigned v = (tid < NB) ? pcnt[tid] : 0u;
    unsigned iv = v;
    #pragma unroll
    for (int o = 1; o < 32; o <<= 1) {
        unsigned y = __shfl_up_sync(0xffffffffu, iv, o);
        if (lane >= o) iv += y;
    }
    if (lane == 31) wsum[wid] = iv;
    __syncthreads();
    if (tid < 32) {
        unsigned a = (tid < 13) ? wsum[tid] : 0u;
        #pragma unroll
        for (int o = 1; o < 32; o <<= 1) {
            unsigned y = __shfl_up_sync(0xffffffffu, a, o);
            if (tid >= o) a += y;
        }
        if (tid < 13) wofs[tid] = a;
    }
    __syncthreads();
    unsigned incl = iv + (wid ? wofs[wid - 1] : 0u);
    if (tid < NB) est[tid] = incl - v;
    if (tid == NB - 1) est[NB] = incl;
    __syncthreads();

    // Phase 3: scatter (conflict-free; slots unique)
    if (tid < NN) {
        sval1[(est[B1] >> 16) + rk1]     = b1;
        sval2[(est[B2] & 0xFFFFu) + rk2] = b2;
    }
    __syncthreads();

    // Phase 4: fused gather per bin r = tid (tid < 384)
    float sq = 0.0f;
    if (tid < RR) {
        unsigned eL = est[tid + 1];
        unsigned eR = est[tid + 8];
        int j0 = (int)(eL >> 16),     j1 = (int)(eR >> 16);
        int k0 = (int)(eL & 0xFFFFu), k1 = (int)(eR & 0xFFFFu);
        int c1 = j1 - j0;
        int c2 = k1 - k0;
        float acc = (float)(j0 - k0) + 0.5f * (float)(c1 - c2);
        float rz  = (float)tid * H250;
        int tot = c1 + c2;
        for (int i = 0; i < tot; i++) {
            bool in1 = i < c1;
            float bv = in1 ? sval1[j0 + i] : sval2[k0 + i - c1];
            float sg = in1 ? 0.5f : -0.5f;
            acc = fmaf(sg, tanh_hw(rz + bv), acc);
        }
        sq = acc * acc;
    }

    // block reduce
    #pragma unroll
    for (int o = 16; o; o >>= 1) sq += __shfl_down_sync(0xffffffffu, sq, o);
    if (lane == 0) ps[wid] = sq;
    __syncthreads();
    if (tid == 0) {
        float s = 0.0f;
        #pragma unroll
        for (int i = 0; i < 13; i++) s += ps[i];
        atomicAdd(&g_loss, s);
        __threadfence();
        unsigned prev = atomicAdd(&g_done, 1u);
        if (prev == (unsigned)(gridDim.x - 1)) {
            g_done = 0u;  // self-reset for graph replay
            float total = *((volatile float*)&g_loss);
            out[0] = total * (1.0f / (float)(RR * TT));
        }
    }
}

extern "C" void kernel_launch(void* const* d_in, const int* in_sizes, int n_in,
                              void* d_out, int out_size) {
    const float* s1 = (const float*)d_in[0];   // [384, 128]
    const float* s2 = (const float*)d_in[1];   // [384, 32]
    float* out = (float*)d_out;

    gen_dirs_kernel<<<240, 256>>>();

    cudaLaunchAttribute attrs[1];
    attrs[0].id = cudaLaunchAttributeProgrammaticStreamSerialization;
    attrs[0].val.programmaticStreamSerializationAllowed = 1;

    {
        cudaLaunchConfig_t cfg = {};
        cfg.gridDim  = dim3(NN / 32, TT / 32, 2);
        cfg.blockDim = dim3(16, 16, 1);
        cfg.stream   = 0;
        cfg.attrs    = attrs;
        cfg.numAttrs = 1;
        if (cudaLaunchKernelEx(&cfg, gemm_kernel, s1, s2) != cudaSuccess)
            gemm_kernel<<<dim3(NN / 32, TT / 32, 2), dim3(16, 16)>>>(s1, s2);
    }
    {
        cudaLaunchConfig_t cfg = {};
        cfg.gridDim  = dim3(TT, 1, 1);
        cfg.blockDim = dim3(ECT_THREADS, 1, 1);
        cfg.stream   = 0;
        cfg.attrs    = attrs;
        cfg.numAttrs = 1;
        if (cudaLaunchKernelEx(&cfg, ect_loss_kernel, out) != cudaSuccess)
            ect_loss_kernel<<<TT, ECT_THREADS>>>(out);
    }
}